// round 5
// baseline (speedup 1.0000x reference)
#include <cuda_runtime.h>
#include <math.h>

#define NS_   6
#define NT_   4
#define B_    2
#define N_    32
#define H_    768
#define W_    768
#define ROI_  28
#define C_    10           // NS + NT
#define L_    39           // 1 + NS + N
#define NEGV  (-100.0f)

#define SEAM_TOT (B_ * H_ * W_)                 // 1179648
#define FULL_OUT (SEAM_TOT + 2 * B_ * L_ + B_)  // 1179806

struct BoxP {
    int y0i, x0i, y1r, x1r;   // strict box (exclusive upper)
    int ys, ye, xs, xe;       // mask box (exclusive upper)
    float ry, rx;             // 28/h, 28/w
    int clsN;                 // thing class 0..3
    int mskoff;               // offset into roi_msk for (b,n,cls)
};

__device__ BoxP g_box[B_ * N_];
__device__ int g_hist[B_ * N_ * C_];
__device__ int g_cstuff[B_ * NS_];
__device__ unsigned char g_pp[B_ * H_ * W_];
__device__ int g_lut[B_ * (NS_ + N_)];

// XLA logistic_expander form: 1 / (1 + exp(-x)). sigmoid(-100) == 0 exactly.
__device__ __forceinline__ float jsig(float x) {
    return __fdiv_rn(1.0f, __fadd_rn(1.0f, expf(-x)));
}

// ---- kernel 0: zero output + scratch, precompute boxes ---------------------
__global__ void __launch_bounds__(256)
k_fill(const float* __restrict__ bbx, const int* __restrict__ cls,
       float* __restrict__ out, int out_size) {
    int gid = blockIdx.x * 256 + threadIdx.x;
    int stride = gridDim.x * 256;
    for (int i = gid; i < out_size; i += stride) out[i] = 0.0f;

    if (blockIdx.x == 0) {
        int t = threadIdx.x;
        for (int i = t; i < B_ * N_ * C_; i += 256) g_hist[i] = 0;
        for (int i = t; i < B_ * NS_; i += 256) g_cstuff[i] = 0;
        if (t < B_ * N_) {
            int b = t / N_, n = t % N_;
            const float* bb = bbx + t * 4;
            float y0f = bb[0], x0f = bb[1], y1f = bb[2], x1f = bb[3];
            int y0 = (int)floorf(y0f), x0 = (int)floorf(x0f);
            int y1 = (int)floorf(y1f), x1 = (int)floorf(x1f);
            int y1r = (int)(rintf(y1f) + 1.0f);   // round-half-even
            int x1r = (int)(rintf(x1f) + 1.0f);
            int hi = y1 - y0 + 1; if (hi < 1) hi = 1;
            int wi = x1 - x0 + 1; if (wi < 1) wi = 1;
            BoxP bp;
            bp.y0i = y0; bp.x0i = x0; bp.y1r = y1r; bp.x1r = x1r;
            bp.ys = max(y0, 0); bp.ye = min(y1 + 1, H_);
            bp.xs = max(x0, 0); bp.xe = min(x1 + 1, W_);
            bp.ry = __fdiv_rn(28.0f, (float)hi);
            bp.rx = __fdiv_rn(28.0f, (float)wi);
            int c = cls[t];
            bp.clsN = c;
            bp.mskoff = ((b * N_ + n) * NT_ + c) * ROI_ * ROI_;
            g_box[t] = bp;
        }
    }
}

// ---- kernel 1: per-pixel fused argmax + histograms (256 thr, 3 px/thr) -----
__global__ void __launch_bounds__(256)
k_main(const float* __restrict__ sem, const float* __restrict__ roi) {
    const int y = blockIdx.x;
    const int b = blockIdx.y;
    const int t = threadIdx.x;

    __shared__ int sh_hist[N_ * C_];
    __shared__ int sh_cst[NS_];
    __shared__ int sh_inYs[N_], sh_inYm[N_];
    __shared__ int sh_x0[N_], sh_x1r[N_], sh_xs[N_], sh_xe[N_], sh_cls[N_];
    __shared__ int sh_r0off[N_], sh_r1off[N_];
    __shared__ float sh_wy[N_], sh_rx[N_];

    for (int i = t; i < N_ * C_; i += 256) sh_hist[i] = 0;
    if (t < NS_) sh_cst[t] = 0;

    if (t < N_) {
        BoxP bp = g_box[b * N_ + t];
        int inYs = (y >= bp.y0i) && (y < bp.y1r);
        int inYm = (y >= bp.ys) && (y < bp.ye);
        sh_inYs[t] = inYs; sh_inYm[t] = inYm;
        sh_x0[t] = bp.x0i; sh_x1r[t] = bp.x1r;
        sh_xs[t] = bp.xs;  sh_xe[t] = bp.xe;
        sh_cls[t] = bp.clsN; sh_rx[t] = bp.rx;
        if (inYm) {
            float sy = __fsub_rn(
                __fmul_rn(__fadd_rn(__fsub_rn((float)y, (float)bp.y0i), 0.5f), bp.ry),
                0.5f);
            sy = fminf(fmaxf(sy, 0.0f), 27.0f);
            float fiy0 = floorf(sy);
            int iy0 = (int)fiy0;
            int iy1 = min(iy0 + 1, ROI_ - 1);
            sh_wy[t] = __fsub_rn(sy, fiy0);
            sh_r0off[t] = bp.mskoff + iy0 * ROI_;
            sh_r1off[t] = bp.mskoff + iy1 * ROI_;
        } else {
            sh_wy[t] = 0.0f; sh_r0off[t] = 0; sh_r1off[t] = 0;
        }
    }
    __syncthreads();

    const float sneg = jsig(NEGV);
    const float C_OUT = __fmul_rn(__fadd_rn(sneg, sneg), __fadd_rn(NEGV, NEGV));
    const float* semb0 = sem + (size_t)b * (C_ * H_ * W_) + (size_t)y * W_;

    for (int px = 0; px < W_ / 256; px++) {
        const int x = t + px * 256;

        float s[C_];
#pragma unroll
        for (int c = 0; c < C_; c++) s[c] = __ldg(semb0 + (size_t)c * (H_ * W_) + x);

        int sem_pred = 0; float sb = s[0];
#pragma unroll
        for (int c = 1; c < C_; c++) if (s[c] > sb) { sb = s[c]; sem_pred = c; }

        float best = s[0]; int bi = 0;
#pragma unroll
        for (int c = 1; c < NS_; c++) if (s[c] > best) { best = s[c]; bi = c; }

        for (int n = 0; n < N_; n++) {
            float v;
            if (!sh_inYs[n]) {
                v = C_OUT;
            } else {
                bool sxin = (x >= sh_x0[n]) && (x < sh_x1r[n]);
                bool mxin = sh_inYm[n] && (x >= sh_xs[n]) && (x < sh_xe[n]);
                if (!sxin && !mxin) {
                    v = C_OUT;
                } else {
                    float a = sxin ? s[NS_ + sh_cls[n]] : NEGV;
                    float m;
                    if (mxin) {
                        float sx = __fsub_rn(
                            __fmul_rn(__fadd_rn(__fsub_rn((float)x, (float)sh_x0[n]), 0.5f),
                                      sh_rx[n]),
                            0.5f);
                        sx = fminf(fmaxf(sx, 0.0f), 27.0f);
                        float fix0 = floorf(sx);
                        int ix0 = (int)fix0;
                        int ix1 = min(ix0 + 1, ROI_ - 1);
                        float wx = __fsub_rn(sx, fix0);
                        const float* r0 = roi + sh_r0off[n];
                        const float* r1 = roi + sh_r1off[n];
                        float wy = sh_wy[n];
                        float omy = __fsub_rn(1.0f, wy);
                        float c0 = __fadd_rn(__fmul_rn(__ldg(r0 + ix0), omy),
                                             __fmul_rn(__ldg(r1 + ix0), wy));
                        float c1 = __fadd_rn(__fmul_rn(__ldg(r0 + ix1), omy),
                                             __fmul_rn(__ldg(r1 + ix1), wy));
                        float omx = __fsub_rn(1.0f, wx);
                        m = __fadd_rn(__fmul_rn(c0, omx), __fmul_rn(c1, wx));
                    } else {
                        m = NEGV;
                    }
                    v = __fmul_rn(__fadd_rn(jsig(a), jsig(m)), __fadd_rn(a, m));
                }
            }
            if (v > best) { best = v; bi = NS_ + n; }
        }

        g_pp[((size_t)b * H_ + y) * W_ + x] = (unsigned char)bi;
        if (bi >= NS_) atomicAdd(&sh_hist[(bi - NS_) * C_ + sem_pred], 1);
        else           atomicAdd(&sh_cst[bi], 1);
    }
    __syncthreads();

    for (int i = t; i < N_ * C_; i += 256) {
        int v = sh_hist[i];
        if (v) atomicAdd(&g_hist[b * N_ * C_ + i], v);
    }
    if (t < NS_) {
        int v = sh_cst[t];
        if (v) atomicAdd(&g_cstuff[b * NS_ + t], v);
    }
}

// ---- kernel 2: per-instance relabel + small outputs (as float) -------------
__global__ void __launch_bounds__(32)
k_post(const int* __restrict__ cls, float* __restrict__ out, int out_size) {
    int b = threadIdx.x;
    if (b >= B_) return;
    const int* hist = g_hist + b * N_ * C_;

    int kept[N_], semlab[N_], total_[N_];
    for (int n = 0; n < N_; n++) {
        int tot = 0;
        for (int c = 0; c < C_; c++) tot += hist[n * C_ + c];
        int smax = 0, mc = hist[n * C_ + 0];
        for (int c = 1; c < C_; c++) {
            int h = hist[n * C_ + c];
            if (h > mc) { mc = h; smax = c; }
        }
        int pres = (tot > 0);
        int tmp = cls[b * N_ + n] + NS_;
        int br1 = (smax == tmp);
        int br2 = (!br1) && (2 * mc >= tot) && (smax < NS_) && pres;
        semlab[n] = br2 ? smax : tmp;
        kept[n] = pres && !br2;
        total_[n] = tot;
    }

    int sp[NS_];
    for (int c = 0; c < NS_; c++) sp[c] = g_cstuff[b * NS_ + c];
    for (int n = 0; n < N_; n++)
        if (semlab[n] < NS_) sp[semlab[n]] += total_[n];

    int srank[NS_]; int nst = 0;
    for (int c = 0; c < NS_; c++) { if (sp[c] > 0) nst++; srank[c] = nst - 1; }

    int* lut = g_lut + b * (NS_ + N_);
    for (int c = 0; c < NS_; c++) lut[c] = srank[c] + 1;

    int rank_k[N_]; int rk = 0;
    for (int n = 0; n < N_; n++) { rank_k[n] = rk; if (kept[n]) rk++; }

    for (int n = 0; n < N_; n++) {
        int v;
        if (kept[n]) v = 1 + nst + rank_k[n];
        else {
            int sl = semlab[n];
            v = (sl < NS_) ? (srank[sl] + 1) : 0;
        }
        lut[NS_ + n] = v;
    }

    if (out_size >= FULL_OUT) {
        int base = SEAM_TOT;
        float* pcls = out + base + b * L_;
        float* pisc = out + base + B_ * L_ + b * L_;
        float* pvl  = out + base + 2 * B_ * L_;
        for (int j = 0; j < L_; j++) pcls[j] = -1.0f;
        pcls[0] = 255.0f;
        for (int c = 0; c < NS_; c++) if (sp[c] > 0) pcls[1 + srank[c]] = (float)c;
        for (int n = 0; n < N_; n++)
            if (kept[n]) pcls[1 + nst + rank_k[n]] = (float)(cls[b * N_ + n] + NS_);
        int vl = 1 + nst + rk;
        for (int j = 0; j < L_; j++) pisc[j] = (j < vl) ? 0.0f : -1.0f;
        pvl[b] = (float)vl;
    }
}

// ---- kernel 3: LUT remap to seamless output (as float) ---------------------
__global__ void __launch_bounds__(256)
k_out(float* __restrict__ out, int nseam) {
    __shared__ float lut[B_ * (NS_ + N_)];
    int t = threadIdx.x;
    if (t < B_ * (NS_ + N_)) lut[t] = (float)g_lut[t];
    __syncthreads();
    int i = blockIdx.x * 256 + t;
    if (i < nseam) {
        int p = (int)g_pp[i];
        int b = i / (H_ * W_);
        out[i] = lut[b * (NS_ + N_) + p];
    }
}

extern "C" void kernel_launch(void* const* d_in, const int* in_sizes, int n_in,
                              void* d_out, int out_size) {
    // Bind inputs by disjoint size ranges (element or byte counts both work):
    // sem 11796480 el / 47MB; roi 200704 el / 800KB; bbx 256 el / 1KB; cls 64 el / 256B.
    const float* sem = nullptr;
    const float* roi = nullptr;
    const float* bbx = nullptr;
    const int*   cls = nullptr;
    for (int i = 0; i < n_in; i++) {
        long long s = in_sizes[i];
        if (s >= 4000000)                 sem = (const float*)d_in[i];
        else if (s >= 100000)             roi = (const float*)d_in[i];
        else if (s >= 512 && s <= 4096)   bbx = (const float*)d_in[i];
        else if (s == 256) { if (!bbx) bbx = (const float*)d_in[i]; }
        else if (s <= 255)                cls = (const int*)d_in[i];
    }
    if (!sem) sem = (const float*)d_in[0];
    if (!roi) roi = (const float*)d_in[1];
    if (!bbx) bbx = (const float*)d_in[2];
    if (!cls) cls = (const int*)d_in[3];
    if (!cls) cls = (const int*)d_in[3];

    float* out = (float*)d_out;

    k_fill<<<1024, 256>>>(bbx, cls, out, out_size);
    dim3 g1(H_, B_);
    k_main<<<g1, 256>>>(sem, roi);
    k_post<<<1, 32>>>(cls, out, out_size);
    int nseam = out_size < SEAM_TOT ? out_size : SEAM_TOT;
    k_out<<<(nseam + 255) / 256, 256>>>(out, nseam);
}

// round 6
// speedup vs baseline: 1.3626x; 1.3626x over previous
#include <cuda_runtime.h>
#include <math.h>

#define NS_   6
#define NT_   4
#define B_    2
#define N_    32
#define H_    768
#define W_    768
#define ROI_  28
#define C_    10           // NS + NT
#define L_    39           // 1 + NS + N
#define NEGV  (-100.0f)

#define SEAM_TOT (B_ * H_ * W_)                 // 1179648
#define FULL_OUT (SEAM_TOT + 2 * B_ * L_ + B_)  // 1179806

struct BoxP {
    int y0i, x0i, y1r, x1r;   // strict box (exclusive upper)
    int ys, ye, xs, xe;       // mask box (exclusive upper)
    float ry, rx;             // 28/h, 28/w
    int clsN;                 // thing class 0..3
    int mskoff;               // offset into roi_msk for (b,n,cls)
};

__device__ BoxP g_box[B_ * N_];
__device__ int g_hist[B_ * N_ * C_];
__device__ int g_cstuff[B_ * NS_];
__device__ __align__(16) unsigned char g_pp[B_ * H_ * W_];
__device__ int g_lut[B_ * (NS_ + N_)];

// XLA logistic_expander form: 1 / (1 + exp(-x)). sigmoid(-100) == 0 exactly.
__device__ __forceinline__ float jsig(float x) {
    return __fdiv_rn(1.0f, __fadd_rn(1.0f, expf(-x)));
}

// ---- kernel 0: zero scratch + residual out, precompute boxes ---------------
__global__ void __launch_bounds__(256)
k_fill(const float* __restrict__ bbx, const int* __restrict__ cls,
       float* __restrict__ out, int out_size) {
    int t = threadIdx.x;
    for (int i = t; i < B_ * N_ * C_; i += 256) g_hist[i] = 0;
    for (int i = t; i < B_ * NS_; i += 256) g_cstuff[i] = 0;
    // zero any residual output beyond what k_out/k_post write
    for (int i = FULL_OUT + t; i < out_size; i += 256) out[i] = 0.0f;

    if (t < B_ * N_) {
        int b = t / N_, n = t % N_;
        const float* bb = bbx + t * 4;
        float y0f = bb[0], x0f = bb[1], y1f = bb[2], x1f = bb[3];
        int y0 = (int)floorf(y0f), x0 = (int)floorf(x0f);
        int y1 = (int)floorf(y1f), x1 = (int)floorf(x1f);
        int y1r = (int)(rintf(y1f) + 1.0f);   // round-half-even
        int x1r = (int)(rintf(x1f) + 1.0f);
        int hi = y1 - y0 + 1; if (hi < 1) hi = 1;
        int wi = x1 - x0 + 1; if (wi < 1) wi = 1;
        BoxP bp;
        bp.y0i = y0; bp.x0i = x0; bp.y1r = y1r; bp.x1r = x1r;
        bp.ys = max(y0, 0); bp.ye = min(y1 + 1, H_);
        bp.xs = max(x0, 0); bp.xe = min(x1 + 1, W_);
        bp.ry = __fdiv_rn(28.0f, (float)hi);
        bp.rx = __fdiv_rn(28.0f, (float)wi);
        int c = cls[t];
        bp.clsN = c;
        bp.mskoff = ((b * N_ + n) * NT_ + c) * ROI_ * ROI_;
        g_box[t] = bp;
    }
}

// ---- kernel 1: per-pixel fused argmax + histograms -------------------------
// One block per (row, batch); 256 threads x 3 pixels. Row-active instances are
// compacted once per block; the per-pixel loop only visits those (~5 of 32).
// All skipped instances contribute C_OUT = -0.0 exactly; since `best` is
// monotone, C_OUT can win at most once, at the FIRST skipped index while
// best < 0 — emulated by a gap check before each active entry + trailing check.
__global__ void __launch_bounds__(256)
k_main(const float* __restrict__ sem, const float* __restrict__ roi) {
    const int y = blockIdx.x;
    const int b = blockIdx.y;
    const int t = threadIdx.x;

    __shared__ int sh_hist[N_ * C_];
    __shared__ int sh_cst[NS_];
    __shared__ int sh_K;
    __shared__ int sa_n[N_], sa_x0[N_], sa_x1r[N_], sa_xs[N_], sa_xe[N_];
    __shared__ int sa_inYm[N_], sa_cls[N_], sa_r0[N_], sa_r1[N_];
    __shared__ float sa_wy[N_], sa_rx[N_];

    for (int i = t; i < N_ * C_; i += 256) sh_hist[i] = 0;
    if (t < NS_) sh_cst[t] = 0;

    if (t < 32) {
        BoxP bp = g_box[b * N_ + t];
        bool inYs = (y >= bp.y0i) && (y < bp.y1r);
        unsigned mask = __ballot_sync(0xffffffffu, inYs);
        if (t == 0) sh_K = __popc(mask);
        if (inYs) {
            int slot = __popc(mask & ((1u << t) - 1u));
            sa_n[slot] = t;
            sa_x0[slot] = bp.x0i; sa_x1r[slot] = bp.x1r;
            sa_xs[slot] = bp.xs;  sa_xe[slot] = bp.xe;
            sa_cls[slot] = bp.clsN; sa_rx[slot] = bp.rx;
            int inYm = (y >= bp.ys) && (y < bp.ye);
            sa_inYm[slot] = inYm;
            if (inYm) {
                float sy = __fsub_rn(
                    __fmul_rn(__fadd_rn(__fsub_rn((float)y, (float)bp.y0i), 0.5f), bp.ry),
                    0.5f);
                sy = fminf(fmaxf(sy, 0.0f), 27.0f);
                float fiy0 = floorf(sy);
                int iy0 = (int)fiy0;
                int iy1 = min(iy0 + 1, ROI_ - 1);
                sa_wy[slot] = __fsub_rn(sy, fiy0);
                sa_r0[slot] = bp.mskoff + iy0 * ROI_;
                sa_r1[slot] = bp.mskoff + iy1 * ROI_;
            } else {
                sa_wy[slot] = 0.0f; sa_r0[slot] = 0; sa_r1[slot] = 0;
            }
        }
    }
    __syncthreads();

    const int K = sh_K;
    const float C_OUT = -0.0f;   // (sig(-100)+sig(-100)) * (-200) with sig(-100)==0
    const float* semb0 = sem + (size_t)b * (C_ * H_ * W_) + (size_t)y * W_;

    for (int px = 0; px < W_ / 256; px++) {
        const int x = t + px * 256;

        float s[C_];
#pragma unroll
        for (int c = 0; c < C_; c++) s[c] = __ldg(semb0 + (size_t)c * (H_ * W_) + x);

        int sem_pred = 0; float sb = s[0];
#pragma unroll
        for (int c = 1; c < C_; c++) if (s[c] > sb) { sb = s[c]; sem_pred = c; }

        float best = s[0]; int bi = 0;
#pragma unroll
        for (int c = 1; c < NS_; c++) if (s[c] > best) { best = s[c]; bi = c; }

        int nextn = 0;   // next unprocessed instance index
        for (int k = 0; k < K; k++) {
            int n = sa_n[k];
            // gap of row-inactive instances [nextn, n): all C_OUT
            if (n > nextn && best < 0.0f) { best = C_OUT; bi = NS_ + nextn; }
            nextn = n + 1;

            bool sxin = (x >= sa_x0[k]) && (x < sa_x1r[k]);
            bool mxin = sa_inYm[k] && (x >= sa_xs[k]) && (x < sa_xe[k]);
            float v;
            if (!sxin && !mxin) {
                v = C_OUT;
            } else {
                float a = sxin ? s[NS_ + sa_cls[k]] : NEGV;
                float m;
                if (mxin) {
                    float sx = __fsub_rn(
                        __fmul_rn(__fadd_rn(__fsub_rn((float)x, (float)sa_x0[k]), 0.5f),
                                  sa_rx[k]),
                        0.5f);
                    sx = fminf(fmaxf(sx, 0.0f), 27.0f);
                    float fix0 = floorf(sx);
                    int ix0 = (int)fix0;
                    int ix1 = min(ix0 + 1, ROI_ - 1);
                    float wx = __fsub_rn(sx, fix0);
                    const float* r0 = roi + sa_r0[k];
                    const float* r1 = roi + sa_r1[k];
                    float wy = sa_wy[k];
                    float omy = __fsub_rn(1.0f, wy);
                    float c0 = __fadd_rn(__fmul_rn(__ldg(r0 + ix0), omy),
                                         __fmul_rn(__ldg(r1 + ix0), wy));
                    float c1 = __fadd_rn(__fmul_rn(__ldg(r0 + ix1), omy),
                                         __fmul_rn(__ldg(r1 + ix1), wy));
                    float omx = __fsub_rn(1.0f, wx);
                    m = __fadd_rn(__fmul_rn(c0, omx), __fmul_rn(c1, wx));
                } else {
                    m = NEGV;
                }
                v = __fmul_rn(__fadd_rn(jsig(a), jsig(m)), __fadd_rn(a, m));
            }
            if (v > best) { best = v; bi = NS_ + n; }
        }
        // trailing gap [nextn, N)
        if (nextn < N_ && best < 0.0f) { best = C_OUT; bi = NS_ + nextn; }

        g_pp[((size_t)b * H_ + y) * W_ + x] = (unsigned char)bi;
        if (bi >= NS_) atomicAdd(&sh_hist[(bi - NS_) * C_ + sem_pred], 1);
        else           atomicAdd(&sh_cst[bi], 1);
    }
    __syncthreads();

    for (int i = t; i < N_ * C_; i += 256) {
        int v = sh_hist[i];
        if (v) atomicAdd(&g_hist[b * N_ * C_ + i], v);
    }
    if (t < NS_) {
        int v = sh_cst[t];
        if (v) atomicAdd(&g_cstuff[b * NS_ + t], v);
    }
}

// ---- kernel 2: per-instance relabel + small outputs (as float) -------------
__global__ void __launch_bounds__(32)
k_post(const int* __restrict__ cls, float* __restrict__ out, int out_size) {
    int b = threadIdx.x;
    if (b >= B_) return;
    const int* hist = g_hist + b * N_ * C_;

    int kept[N_], semlab[N_], total_[N_];
    for (int n = 0; n < N_; n++) {
        int tot = 0;
        for (int c = 0; c < C_; c++) tot += hist[n * C_ + c];
        int smax = 0, mc = hist[n * C_ + 0];
        for (int c = 1; c < C_; c++) {
            int h = hist[n * C_ + c];
            if (h > mc) { mc = h; smax = c; }
        }
        int pres = (tot > 0);
        int tmp = cls[b * N_ + n] + NS_;
        int br1 = (smax == tmp);
        int br2 = (!br1) && (2 * mc >= tot) && (smax < NS_) && pres;
        semlab[n] = br2 ? smax : tmp;
        kept[n] = pres && !br2;
        total_[n] = tot;
    }

    int sp[NS_];
    for (int c = 0; c < NS_; c++) sp[c] = g_cstuff[b * NS_ + c];
    for (int n = 0; n < N_; n++)
        if (semlab[n] < NS_) sp[semlab[n]] += total_[n];

    int srank[NS_]; int nst = 0;
    for (int c = 0; c < NS_; c++) { if (sp[c] > 0) nst++; srank[c] = nst - 1; }

    int* lut = g_lut + b * (NS_ + N_);
    for (int c = 0; c < NS_; c++) lut[c] = srank[c] + 1;

    int rank_k[N_]; int rk = 0;
    for (int n = 0; n < N_; n++) { rank_k[n] = rk; if (kept[n]) rk++; }

    for (int n = 0; n < N_; n++) {
        int v;
        if (kept[n]) v = 1 + nst + rank_k[n];
        else {
            int sl = semlab[n];
            v = (sl < NS_) ? (srank[sl] + 1) : 0;
        }
        lut[NS_ + n] = v;
    }

    if (out_size >= FULL_OUT) {
        int base = SEAM_TOT;
        float* pcls = out + base + b * L_;
        float* pisc = out + base + B_ * L_ + b * L_;
        float* pvl  = out + base + 2 * B_ * L_;
        for (int j = 0; j < L_; j++) pcls[j] = -1.0f;
        pcls[0] = 255.0f;
        for (int c = 0; c < NS_; c++) if (sp[c] > 0) pcls[1 + srank[c]] = (float)c;
        for (int n = 0; n < N_; n++)
            if (kept[n]) pcls[1 + nst + rank_k[n]] = (float)(cls[b * N_ + n] + NS_);
        int vl = 1 + nst + rk;
        for (int j = 0; j < L_; j++) pisc[j] = (j < vl) ? 0.0f : -1.0f;
        pvl[b] = (float)vl;
    }
}

// ---- kernel 3: LUT remap, 4 px/thread, 128-bit stores ----------------------
__global__ void __launch_bounds__(256)
k_out(float* __restrict__ out) {
    __shared__ float lut[B_ * (NS_ + N_)];
    int t = threadIdx.x;
    if (t < B_ * (NS_ + N_)) lut[t] = (float)g_lut[t];
    __syncthreads();
    int i = blockIdx.x * 256 + t;              // quad index
    const int tot = SEAM_TOT / 4;
    if (i < tot) {
        unsigned int p = ((const unsigned int*)g_pp)[i];
        int b = (i * 4) / (H_ * W_);           // H*W divisible by 4 -> same b for quad
        const float* l = lut + b * (NS_ + N_);
        float4 o;
        o.x = l[p & 0xFF];
        o.y = l[(p >> 8) & 0xFF];
        o.z = l[(p >> 16) & 0xFF];
        o.w = l[(p >> 24) & 0xFF];
        ((float4*)out)[i] = o;
    }
}

extern "C" void kernel_launch(void* const* d_in, const int* in_sizes, int n_in,
                              void* d_out, int out_size) {
    const float* sem = nullptr;
    const float* roi = nullptr;
    const float* bbx = nullptr;
    const int*   cls = nullptr;
    for (int i = 0; i < n_in; i++) {
        long long s = in_sizes[i];
        if (s >= 4000000)                 sem = (const float*)d_in[i];
        else if (s >= 100000)             roi = (const float*)d_in[i];
        else if (s >= 512 && s <= 4096)   bbx = (const float*)d_in[i];
        else if (s == 256) { if (!bbx) bbx = (const float*)d_in[i]; }
        else if (s <= 255)                cls = (const int*)d_in[i];
    }
    if (!sem) sem = (const float*)d_in[0];
    if (!roi) roi = (const float*)d_in[1];
    if (!bbx) bbx = (const float*)d_in[2];
    if (!cls) cls = (const int*)d_in[3];

    float* out = (float*)d_out;

    k_fill<<<1, 256>>>(bbx, cls, out, out_size);
    dim3 g1(H_, B_);
    k_main<<<g1, 256>>>(sem, roi);
    k_post<<<1, 32>>>(cls, out, out_size);
    k_out<<<(SEAM_TOT / 4 + 255) / 256, 256>>>(out);
}

// round 7
// speedup vs baseline: 1.6650x; 1.2219x over previous
#include <cuda_runtime.h>
#include <math.h>

#define NS_   6
#define NT_   4
#define B_    2
#define N_    32
#define H_    768
#define W_    768
#define ROI_  28
#define C_    10           // NS + NT
#define L_    39           // 1 + NS + N
#define NEGV  (-100.0f)

#define SEAM_TOT (B_ * H_ * W_)                 // 1179648
#define FULL_OUT (SEAM_TOT + 2 * B_ * L_ + B_)  // 1179806

struct BoxP {
    int y0i, x0i, y1r, x1r;   // strict box (exclusive upper)
    int ys, ye, xs, xe;       // mask box (exclusive upper); subset of strict box
    float ry, rx;             // 28/h, 28/w
    int clsN;                 // thing class 0..3
    int mskoff;               // offset into roi_msk for (b,n,cls)
};

__device__ BoxP g_box[B_ * N_];
__device__ int g_hist[B_ * N_ * C_];
__device__ int g_cstuff[B_ * NS_];
__device__ __align__(16) unsigned char g_pp[B_ * H_ * W_];
__device__ float g_lutf[B_ * (NS_ + N_)];

// XLA logistic_expander form: 1 / (1 + exp(-x)). sigmoid(-100) == 0 exactly.
__device__ __forceinline__ float jsig(float x) {
    return __fdiv_rn(1.0f, __fadd_rn(1.0f, expf(-x)));
}

// ---- kernel 0: zero scratch + residual out, precompute boxes ---------------
__global__ void __launch_bounds__(256)
k_fill(const float* __restrict__ bbx, const int* __restrict__ cls,
       float* __restrict__ out, int out_size) {
    int t = threadIdx.x;
    for (int i = t; i < B_ * N_ * C_; i += 256) g_hist[i] = 0;
    for (int i = t; i < B_ * NS_; i += 256) g_cstuff[i] = 0;
    for (int i = FULL_OUT + t; i < out_size; i += 256) out[i] = 0.0f;

    if (t < B_ * N_) {
        int b = t / N_, n = t % N_;
        const float* bb = bbx + t * 4;
        float y0f = bb[0], x0f = bb[1], y1f = bb[2], x1f = bb[3];
        int y0 = (int)floorf(y0f), x0 = (int)floorf(x0f);
        int y1 = (int)floorf(y1f), x1 = (int)floorf(x1f);
        int y1r = (int)(rintf(y1f) + 1.0f);   // round-half-even
        int x1r = (int)(rintf(x1f) + 1.0f);
        int hi = y1 - y0 + 1; if (hi < 1) hi = 1;
        int wi = x1 - x0 + 1; if (wi < 1) wi = 1;
        BoxP bp;
        bp.y0i = y0; bp.x0i = x0; bp.y1r = y1r; bp.x1r = x1r;
        bp.ys = max(y0, 0); bp.ye = min(y1 + 1, H_);
        bp.xs = max(x0, 0); bp.xe = min(x1 + 1, W_);
        bp.ry = __fdiv_rn(28.0f, (float)hi);
        bp.rx = __fdiv_rn(28.0f, (float)wi);
        int c = cls[t];
        bp.clsN = c;
        bp.mskoff = ((b * N_ + n) * NT_ + c) * ROI_ * ROI_;
        g_box[t] = bp;
    }
}

// ---- kernel 1: per-pixel fused argmax + histograms -------------------------
// Row-active instances compacted once per block; then per (warp, 256-px tile)
// a ballot narrows to instances intersecting the warp's 32-px window (~1).
// All non-covering instances contribute C_OUT = -0.0 exactly, applied at the
// first skipped index via gap logic (argmax order semantics preserved).
// NOTE: mask box is a subset of the strict box (xs>=x0, xe<=x1r, same in y),
// so "pixel covered" <=> sxin.
__global__ void __launch_bounds__(256)
k_main(const float* __restrict__ sem, const float* __restrict__ roi) {
    const int y = blockIdx.x;
    const int b = blockIdx.y;
    const int t = threadIdx.x;
    const int lane = t & 31;

    __shared__ int sh_hist[N_ * C_];
    __shared__ int sh_cst[NS_];
    __shared__ int sh_K;
    __shared__ int sa_n[N_], sa_x0[N_], sa_x1r[N_], sa_xs[N_], sa_xe[N_];
    __shared__ int sa_inYm[N_], sa_cls[N_], sa_r0[N_], sa_r1[N_];
    __shared__ float sa_wy[N_], sa_rx[N_];

    for (int i = t; i < N_ * C_; i += 256) sh_hist[i] = 0;
    if (t < NS_) sh_cst[t] = 0;

    if (t < 32) {
        BoxP bp = g_box[b * N_ + t];
        bool inYs = (y >= bp.y0i) && (y < bp.y1r);
        unsigned mask = __ballot_sync(0xffffffffu, inYs);
        if (t == 0) sh_K = __popc(mask);
        if (inYs) {
            int slot = __popc(mask & ((1u << t) - 1u));
            sa_n[slot] = t;
            sa_x0[slot] = bp.x0i; sa_x1r[slot] = bp.x1r;
            sa_xs[slot] = bp.xs;  sa_xe[slot] = bp.xe;
            sa_cls[slot] = bp.clsN; sa_rx[slot] = bp.rx;
            int inYm = (y >= bp.ys) && (y < bp.ye);
            sa_inYm[slot] = inYm;
            if (inYm) {
                float sy = __fsub_rn(
                    __fmul_rn(__fadd_rn(__fsub_rn((float)y, (float)bp.y0i), 0.5f), bp.ry),
                    0.5f);
                sy = fminf(fmaxf(sy, 0.0f), 27.0f);
                float fiy0 = floorf(sy);
                int iy0 = (int)fiy0;
                int iy1 = min(iy0 + 1, ROI_ - 1);
                sa_wy[slot] = __fsub_rn(sy, fiy0);
                sa_r0[slot] = bp.mskoff + iy0 * ROI_;
                sa_r1[slot] = bp.mskoff + iy1 * ROI_;
            } else {
                sa_wy[slot] = 0.0f; sa_r0[slot] = 0; sa_r1[slot] = 0;
            }
        }
    }
    __syncthreads();

    const int K = sh_K;
    const float C_OUT = -0.0f;
    const float* semb0 = sem + (size_t)b * (C_ * H_ * W_) + (size_t)y * W_;

    for (int px = 0; px < W_ / 256; px++) {
        const int x = t + px * 256;

        // warp-level filter: instances whose strict x-interval meets this
        // warp's 32-pixel window
        unsigned wmask;
        {
            int wlo = px * 256 + (t & ~31);
            bool inter = false;
            if (lane < K) inter = (sa_x0[lane] <= wlo + 31) && (sa_x1r[lane] > wlo);
            wmask = __ballot_sync(0xffffffffu, inter);
        }

        float s[C_];
#pragma unroll
        for (int c = 0; c < C_; c++) s[c] = __ldg(semb0 + (size_t)c * (H_ * W_) + x);

        int sem_pred = 0; float sb = s[0];
#pragma unroll
        for (int c = 1; c < C_; c++) if (s[c] > sb) { sb = s[c]; sem_pred = c; }

        float best = s[0]; int bi = 0;
#pragma unroll
        for (int c = 1; c < NS_; c++) if (s[c] > best) { best = s[c]; bi = c; }

        int nextn = 0;
        for (unsigned mrem = wmask; mrem; mrem &= mrem - 1) {
            int k = __ffs(mrem) - 1;
            int n = sa_n[k];
            if (n > nextn && best < 0.0f) { best = C_OUT; bi = NS_ + nextn; }
            nextn = n + 1;

            float v;
            bool sxin = (x >= sa_x0[k]) && (x < sa_x1r[k]);
            if (!sxin) {
                v = C_OUT;
            } else {
                float a = s[NS_ + sa_cls[k]];
                float m;
                bool mxin = sa_inYm[k] && (x >= sa_xs[k]) && (x < sa_xe[k]);
                if (mxin) {
                    float sx = __fsub_rn(
                        __fmul_rn(__fadd_rn(__fsub_rn((float)x, (float)sa_x0[k]), 0.5f),
                                  sa_rx[k]),
                        0.5f);
                    sx = fminf(fmaxf(sx, 0.0f), 27.0f);
                    float fix0 = floorf(sx);
                    int ix0 = (int)fix0;
                    int ix1 = min(ix0 + 1, ROI_ - 1);
                    float wx = __fsub_rn(sx, fix0);
                    const float* r0 = roi + sa_r0[k];
                    const float* r1 = roi + sa_r1[k];
                    float wy = sa_wy[k];
                    float omy = __fsub_rn(1.0f, wy);
                    float c0 = __fadd_rn(__fmul_rn(__ldg(r0 + ix0), omy),
                                         __fmul_rn(__ldg(r1 + ix0), wy));
                    float c1 = __fadd_rn(__fmul_rn(__ldg(r0 + ix1), omy),
                                         __fmul_rn(__ldg(r1 + ix1), wy));
                    float omx = __fsub_rn(1.0f, wx);
                    m = __fadd_rn(__fmul_rn(c0, omx), __fmul_rn(c1, wx));
                } else {
                    m = NEGV;
                }
                v = __fmul_rn(__fadd_rn(jsig(a), jsig(m)), __fadd_rn(a, m));
            }
            if (v > best) { best = v; bi = NS_ + n; }
        }
        if (nextn < N_ && best < 0.0f) { best = C_OUT; bi = NS_ + nextn; }

        g_pp[((size_t)b * H_ + y) * W_ + x] = (unsigned char)bi;
        if (bi >= NS_) atomicAdd(&sh_hist[(bi - NS_) * C_ + sem_pred], 1);
        else           atomicAdd(&sh_cst[bi], 1);
    }
    __syncthreads();

    for (int i = t; i < N_ * C_; i += 256) {
        int v = sh_hist[i];
        if (v) atomicAdd(&g_hist[b * N_ * C_ + i], v);
    }
    if (t < NS_) {
        int v = sh_cst[t];
        if (v) atomicAdd(&g_cstuff[b * NS_ + t], v);
    }
}

// ---- kernel 2: per-instance relabel + small outputs (as float) -------------
__global__ void __launch_bounds__(32)
k_post(const int* __restrict__ cls, float* __restrict__ out, int out_size) {
    int b = threadIdx.x;
    if (b >= B_) return;
    const int* hist = g_hist + b * N_ * C_;

    int kept[N_], semlab[N_], total_[N_];
    for (int n = 0; n < N_; n++) {
        int tot = 0;
        for (int c = 0; c < C_; c++) tot += hist[n * C_ + c];
        int smax = 0, mc = hist[n * C_ + 0];
        for (int c = 1; c < C_; c++) {
            int h = hist[n * C_ + c];
            if (h > mc) { mc = h; smax = c; }
        }
        int pres = (tot > 0);
        int tmp = cls[b * N_ + n] + NS_;
        int br1 = (smax == tmp);
        int br2 = (!br1) && (2 * mc >= tot) && (smax < NS_) && pres;
        semlab[n] = br2 ? smax : tmp;
        kept[n] = pres && !br2;
        total_[n] = tot;
    }

    int sp[NS_];
    for (int c = 0; c < NS_; c++) sp[c] = g_cstuff[b * NS_ + c];
    for (int n = 0; n < N_; n++)
        if (semlab[n] < NS_) sp[semlab[n]] += total_[n];

    int srank[NS_]; int nst = 0;
    for (int c = 0; c < NS_; c++) { if (sp[c] > 0) nst++; srank[c] = nst - 1; }

    float* lut = g_lutf + b * (NS_ + N_);
    for (int c = 0; c < NS_; c++) lut[c] = (float)(srank[c] + 1);

    int rank_k[N_]; int rk = 0;
    for (int n = 0; n < N_; n++) { rank_k[n] = rk; if (kept[n]) rk++; }

    for (int n = 0; n < N_; n++) {
        int v;
        if (kept[n]) v = 1 + nst + rank_k[n];
        else {
            int sl = semlab[n];
            v = (sl < NS_) ? (srank[sl] + 1) : 0;
        }
        lut[NS_ + n] = (float)v;
    }

    if (out_size >= FULL_OUT) {
        int base = SEAM_TOT;
        float* pcls = out + base + b * L_;
        float* pisc = out + base + B_ * L_ + b * L_;
        float* pvl  = out + base + 2 * B_ * L_;
        for (int j = 0; j < L_; j++) pcls[j] = -1.0f;
        pcls[0] = 255.0f;
        for (int c = 0; c < NS_; c++) if (sp[c] > 0) pcls[1 + srank[c]] = (float)c;
        for (int n = 0; n < N_; n++)
            if (kept[n]) pcls[1 + nst + rank_k[n]] = (float)(cls[b * N_ + n] + NS_);
        int vl = 1 + nst + rk;
        for (int j = 0; j < L_; j++) pisc[j] = (j < vl) ? 0.0f : -1.0f;
        pvl[b] = (float)vl;
    }
}

// ---- kernel 3: LUT remap, 4 quads (16 px) per thread, no shared/sync -------
__global__ void __launch_bounds__(256)
k_out(float* __restrict__ out) {
    const int HWQ = H_ * W_ / 4;              // quads per batch image
    int base = blockIdx.x * 1024 + threadIdx.x;
#pragma unroll
    for (int j = 0; j < 4; j++) {
        int i = base + j * 256;               // quad index
        unsigned int p = __ldg((const unsigned int*)g_pp + i);
        const float* l = g_lutf + ((i >= HWQ) ? (NS_ + N_) : 0);
        float4 o;
        o.x = __ldg(l + (p & 0xFF));
        o.y = __ldg(l + ((p >> 8) & 0xFF));
        o.z = __ldg(l + ((p >> 16) & 0xFF));
        o.w = __ldg(l + ((p >> 24) & 0xFF));
        ((float4*)out)[i] = o;
    }
}

extern "C" void kernel_launch(void* const* d_in, const int* in_sizes, int n_in,
                              void* d_out, int out_size) {
    const float* sem = nullptr;
    const float* roi = nullptr;
    const float* bbx = nullptr;
    const int*   cls = nullptr;
    for (int i = 0; i < n_in; i++) {
        long long s = in_sizes[i];
        if (s >= 4000000)                 sem = (const float*)d_in[i];
        else if (s >= 100000)             roi = (const float*)d_in[i];
        else if (s >= 512 && s <= 4096)   bbx = (const float*)d_in[i];
        else if (s == 256) { if (!bbx) bbx = (const float*)d_in[i]; }
        else if (s <= 255)                cls = (const int*)d_in[i];
    }
    if (!sem) sem = (const float*)d_in[0];
    if (!roi) roi = (const float*)d_in[1];
    if (!bbx) bbx = (const float*)d_in[2];
    if (!cls) cls = (const int*)d_in[3];

    float* out = (float*)d_out;

    k_fill<<<1, 256>>>(bbx, cls, out, out_size);
    dim3 g1(H_, B_);
    k_main<<<g1, 256>>>(sem, roi);
    k_post<<<1, 32>>>(cls, out, out_size);
    k_out<<<SEAM_TOT / 4 / 1024, 256>>>(out);   // 288 blocks x 256 thr x 4 quads
}